// round 5
// baseline (speedup 1.0000x reference)
#include <cuda_runtime.h>
#include <cuda_fp16.h>
#include <cstdint>

#define H 128
#define DI 64
#define MAX_N 50000
#define MAX_M 20000
#define MAX_E 1000000
#define SCAN_B 512

// ---------------- scratch (no allocations allowed) ----------------
__device__ float  g_pmsg[MAX_M * H];
__device__ float  g_imsg[MAX_N * H];
__device__ __half g_hitem16[MAX_N * H];   // fp16 gather mirror of h_item
__device__ __half g_hpat16 [MAX_M * H];   // fp16 gather mirror of h_pat
__device__ float  g_whi[4 * H * H];
__device__ float  g_wlo[4 * H * H];
__device__ int    g_i32[MAX_E];           // narrowed item idx
__device__ int    g_p32[MAX_E];           // narrowed pattern idx
__device__ int    g_psrc[MAX_E];
__device__ int    g_isrc[MAX_E];
__device__ int    g_prow[MAX_M + 1];
__device__ int    g_irow[MAX_N + 1];
__device__ int    g_pcur[MAX_M];
__device__ int    g_icur[MAX_N];
__device__ int    g_pcnt[MAX_M];
__device__ int    g_icnt[MAX_N];
__device__ int    g_pbsum[(MAX_M + SCAN_B - 1) / SCAN_B];
__device__ int    g_ibsum[(MAX_N + SCAN_B - 1) / SCAN_B];
__device__ int    g_is64;

// ---------------- index dtype detection ----------------
__global__ void detect_kernel(const unsigned long long* __restrict__ raw, int nsamp) {
    __shared__ int any;
    if (threadIdx.x == 0) any = 0;
    __syncthreads();
    int found = 0;
    for (int i = threadIdx.x; i < nsamp; i += blockDim.x)
        if ((raw[i] >> 32) != 0ULL) found = 1;
    if (found) atomicExch(&any, 1);
    __syncthreads();
    if (threadIdx.x == 0) g_is64 = any ? 0 : 1;
}

__device__ __forceinline__ int load_idx(const void* raw, int e, int is64) {
    return is64 ? (int)((const long long*)raw)[e] : ((const int*)raw)[e];
}

// ---------------- CSR build ----------------
__global__ void zero2_kernel(int* __restrict__ a, int na, int* __restrict__ b, int nb) {
    int i = blockIdx.x * blockDim.x + threadIdx.x;
    if (i < na) a[i] = 0;
    if (i < nb) b[i] = 0;
}

// count + narrow indices to int32 in one pass
__global__ void count_kernel(const void* __restrict__ iraw,
                             const void* __restrict__ praw, int E) {
    int e = blockIdx.x * blockDim.x + threadIdx.x;
    if (e >= E) return;
    int is64 = g_is64;
    int s = load_idx(iraw, e, is64);
    int d = load_idx(praw, e, is64);
    g_i32[e] = s;
    g_p32[e] = d;
    atomicAdd(&g_icnt[s], 1);
    atomicAdd(&g_pcnt[d], 1);
}

__global__ void reduce_counts_kernel(const int* __restrict__ cnt, int n,
                                     int* __restrict__ bsum) {
    __shared__ int sh[SCAN_B];
    int t = threadIdx.x;
    int i = blockIdx.x * SCAN_B + t;
    sh[t] = (i < n) ? cnt[i] : 0;
    __syncthreads();
    for (int s = SCAN_B / 2; s > 0; s >>= 1) {
        if (t < s) sh[t] += sh[t + s];
        __syncthreads();
    }
    if (t == 0) bsum[blockIdx.x] = sh[0];
}

__global__ void scan_bsums_kernel(int* __restrict__ bsum, int nb) {
    __shared__ int sh[1024];
    int t = threadIdx.x;
    int v = (t < nb) ? bsum[t] : 0;
    sh[t] = v;
    __syncthreads();
    for (int off = 1; off < 1024; off <<= 1) {
        int x = (t >= off) ? sh[t - off] : 0;
        __syncthreads();
        sh[t] += x;
        __syncthreads();
    }
    if (t < nb) bsum[t] = sh[t] - v;
}

__global__ void scan_counts_kernel(const int* __restrict__ cnt, int n,
                                   const int* __restrict__ bsum,
                                   int* __restrict__ rowptr,
                                   int* __restrict__ cursor, int E) {
    __shared__ int sh[SCAN_B];
    int t = threadIdx.x;
    int i = blockIdx.x * SCAN_B + t;
    int v = (i < n) ? cnt[i] : 0;
    sh[t] = v;
    __syncthreads();
    for (int off = 1; off < SCAN_B; off <<= 1) {
        int x = (t >= off) ? sh[t - off] : 0;
        __syncthreads();
        sh[t] += x;
        __syncthreads();
    }
    int excl = sh[t] - v + bsum[blockIdx.x];
    if (i < n) { rowptr[i] = excl; cursor[i] = excl; }
    if (i == 0 && blockIdx.x == 0) rowptr[n] = E;
}

__global__ void place_kernel(int E) {
    int e = blockIdx.x * blockDim.x + threadIdx.x;
    if (e >= E) return;
    int s = g_i32[e];
    int d = g_p32[e];
    g_psrc[atomicAdd(&g_pcur[d], 1)] = s;
    g_isrc[atomicAdd(&g_icur[s], 1)] = d;
}

// ---------------- weight split: W -> tf32 hi + tf32 lo ----------------
__device__ __forceinline__ uint32_t to_tf32(float x) {
    uint32_t r;
    asm("cvt.rna.tf32.f32 %0, %1;" : "=r"(r) : "f"(x));
    return r;
}

__global__ void wsplit_kernel(const float* __restrict__ W,
                              float* __restrict__ hi, float* __restrict__ lo, int n) {
    int i = blockIdx.x * blockDim.x + threadIdx.x;
    if (i >= n) return;
    float w = W[i];
    float h = __uint_as_float(to_tf32(w));
    hi[i] = h;
    lo[i] = __uint_as_float(to_tf32(w - h));
}

// ---------------- segmented gather-reduce: fp16 src, fp32 acc, fp32 dst ----------------
// one warp per destination; lane covers 4 halves (8B); 256B read per edge
__global__ __launch_bounds__(256)
void aggregate_kernel(const __half* __restrict__ src, float* __restrict__ dst,
                      const int* __restrict__ row, const int* __restrict__ srcids,
                      int ndst) {
    int w = (int)((blockIdx.x * blockDim.x + threadIdx.x) >> 5);
    if (w >= ndst) return;
    int lane = threadIdx.x & 31;
    int beg = __ldg(row + w);
    int end = __ldg(row + w + 1);
    const __half* sp = src + lane * 4;

    float4 a0 = make_float4(0.f, 0.f, 0.f, 0.f);
    float4 a1 = make_float4(0.f, 0.f, 0.f, 0.f);
    int e = beg;
    for (; e + 1 < end; e += 2) {
        int s0 = __ldg(srcids + e);
        int s1 = __ldg(srcids + e + 1);
        uint2 v0 = *(const uint2*)(sp + (size_t)s0 * H);
        uint2 v1 = *(const uint2*)(sp + (size_t)s1 * H);
        float2 f;
        f = __half22float2(*(__half2*)&v0.x); a0.x += f.x; a0.y += f.y;
        f = __half22float2(*(__half2*)&v0.y); a0.z += f.x; a0.w += f.y;
        f = __half22float2(*(__half2*)&v1.x); a1.x += f.x; a1.y += f.y;
        f = __half22float2(*(__half2*)&v1.y); a1.z += f.x; a1.w += f.y;
    }
    if (e < end) {
        uint2 v0 = *(const uint2*)(sp + (size_t)__ldg(srcids + e) * H);
        float2 f;
        f = __half22float2(*(__half2*)&v0.x); a0.x += f.x; a0.y += f.y;
        f = __half22float2(*(__half2*)&v0.y); a0.z += f.x; a0.w += f.y;
    }
    a0.x += a1.x; a0.y += a1.y; a0.z += a1.z; a0.w += a1.w;
    *(float4*)(dst + (size_t)w * H + lane * 4) = a0;
}

// ---------------- 3xTF32 GEMM: C = relu(A[n,K] @ W[K,128] + b); FUSED: relu(C + that) ----------------
// Writes fp32 C and fp16 mirror C16.
template<int K, bool FUSED>
__global__ __launch_bounds__(256, 2)
void tgemm_kernel(const float* __restrict__ A,
                  const float* __restrict__ Whi, const float* __restrict__ Wlo,
                  const float* __restrict__ bias, float* __restrict__ C,
                  __half* __restrict__ C16, int n) {
    constexpr int BM = 128, BN = 128, BK = 16;
    __shared__ float As[BM][20];
    __shared__ float BsH[BK][136];
    __shared__ float BsL[BK][136];

    const int tid = threadIdx.x;
    const int wid = tid >> 5, lane = tid & 31;
    const int wr = wid >> 1;
    const int wc = wid & 1;
    const int row0 = blockIdx.x * BM;
    const int l4 = lane >> 2, lm = lane & 3;

    float acc[2][8][4];
#pragma unroll
    for (int mi = 0; mi < 2; mi++)
#pragma unroll
        for (int nj = 0; nj < 8; nj++)
#pragma unroll
            for (int q = 0; q < 4; q++) acc[mi][nj][q] = 0.f;

    for (int k0 = 0; k0 < K; k0 += BK) {
#pragma unroll
        for (int i = 0; i < 2; i++) {
            int f = tid + i * 256;
            int r = f >> 2, c4 = (f & 3) * 4;
            int gr = row0 + r;
            float4 v = make_float4(0.f, 0.f, 0.f, 0.f);
            if (gr < n) v = *(const float4*)(A + (size_t)gr * K + k0 + c4);
            *(float4*)&As[r][c4] = v;
        }
#pragma unroll
        for (int i = 0; i < 2; i++) {
            int f = tid + i * 256;
            int r = f >> 5, c4 = (f & 31) * 4;
            *(float4*)&BsH[r][c4] = *(const float4*)(Whi + (size_t)(k0 + r) * BN + c4);
            *(float4*)&BsL[r][c4] = *(const float4*)(Wlo + (size_t)(k0 + r) * BN + c4);
        }
        __syncthreads();

#pragma unroll
        for (int ks = 0; ks < 2; ks++) {
            const int kb = ks * 8 + lm;
            uint32_t ah[2][4], al[2][4];
#pragma unroll
            for (int mi = 0; mi < 2; mi++) {
                int rb = wr * 32 + mi * 16 + l4;
                float av[4];
                av[0] = As[rb][kb];
                av[1] = As[rb + 8][kb];
                av[2] = As[rb][kb + 4];
                av[3] = As[rb + 8][kb + 4];
#pragma unroll
                for (int q = 0; q < 4; q++) {
                    uint32_t hb = to_tf32(av[q]);
                    ah[mi][q] = hb;
                    al[mi][q] = to_tf32(av[q] - __uint_as_float(hb));
                }
            }
#pragma unroll
            for (int nj = 0; nj < 8; nj++) {
                int nn = wc * 64 + nj * 8 + l4;
                uint32_t bh0 = __float_as_uint(BsH[kb][nn]);
                uint32_t bh1 = __float_as_uint(BsH[kb + 4][nn]);
                uint32_t bl0 = __float_as_uint(BsL[kb][nn]);
                uint32_t bl1 = __float_as_uint(BsL[kb + 4][nn]);
#pragma unroll
                for (int mi = 0; mi < 2; mi++) {
                    float* d = acc[mi][nj];
#define TMMA(A0,A1,A2,A3,B0,B1) \
    asm volatile("mma.sync.aligned.m16n8k8.row.col.f32.tf32.tf32.f32 " \
        "{%0,%1,%2,%3},{%4,%5,%6,%7},{%8,%9},{%0,%1,%2,%3};" \
        : "+f"(d[0]), "+f"(d[1]), "+f"(d[2]), "+f"(d[3]) \
        : "r"(A0), "r"(A1), "r"(A2), "r"(A3), "r"(B0), "r"(B1))
                    TMMA(ah[mi][0], ah[mi][1], ah[mi][2], ah[mi][3], bh0, bh1);
                    TMMA(al[mi][0], al[mi][1], al[mi][2], al[mi][3], bh0, bh1);
                    TMMA(ah[mi][0], ah[mi][1], ah[mi][2], ah[mi][3], bl0, bl1);
#undef TMMA
                }
            }
        }
        __syncthreads();
    }

#pragma unroll
    for (int mi = 0; mi < 2; mi++) {
#pragma unroll
        for (int hh = 0; hh < 2; hh++) {
            int r = row0 + wr * 32 + mi * 16 + l4 + hh * 8;
            if (r >= n) continue;
#pragma unroll
            for (int nj = 0; nj < 8; nj++) {
                int cc = wc * 64 + nj * 8 + lm * 2;
                float x0 = fmaxf(acc[mi][nj][hh * 2 + 0] + __ldg(bias + cc), 0.f);
                float x1 = fmaxf(acc[mi][nj][hh * 2 + 1] + __ldg(bias + cc + 1), 0.f);
                if (FUSED) {
                    float2 rv = *(const float2*)(C + (size_t)r * BN + cc);
                    x0 = fmaxf(rv.x + x0, 0.f);
                    x1 = fmaxf(rv.y + x1, 0.f);
                }
                *(float2*)(C + (size_t)r * BN + cc) = make_float2(x0, x1);
                *(__half2*)(C16 + (size_t)r * BN + cc) = __floats2half2_rn(x0, x1);
            }
        }
    }
}

// ---------------- launch ----------------
extern "C" void kernel_launch(void* const* d_in, const int* in_sizes, int n_in,
                              void* d_out, int out_size) {
    const float* item_feat = (const float*)d_in[0];
    const float* pat_feat  = (const float*)d_in[1];
    const void*  iidx_raw  = d_in[2];
    const void*  pidx_raw  = d_in[3];
    const float* W_item = (const float*)d_in[4];
    const float* b_item = (const float*)d_in[5];
    const float* W_pat  = (const float*)d_in[6];
    const float* b_pat  = (const float*)d_in[7];
    const float* W_i2p  = (const float*)d_in[8];
    const float* b_i2p  = (const float*)d_in[9];
    const float* W_p2i  = (const float*)d_in[10];
    const float* b_p2i  = (const float*)d_in[11];

    const int N_ = in_sizes[0] / DI;
    const int M_ = in_sizes[1] / DI;
    const int E_ = in_sizes[2];

    float* h_item = (float*)d_out;
    float* h_pat  = (float*)d_out + (size_t)N_ * H;

    void* p;
    cudaGetSymbolAddress(&p, g_pmsg);    float*  pmsg    = (float*)p;
    cudaGetSymbolAddress(&p, g_imsg);    float*  imsg    = (float*)p;
    cudaGetSymbolAddress(&p, g_hitem16); __half* hitem16 = (__half*)p;
    cudaGetSymbolAddress(&p, g_hpat16);  __half* hpat16  = (__half*)p;
    cudaGetSymbolAddress(&p, g_whi);     float*  whi     = (float*)p;
    cudaGetSymbolAddress(&p, g_wlo);     float*  wlo     = (float*)p;
    cudaGetSymbolAddress(&p, g_psrc);    int* psrc  = (int*)p;
    cudaGetSymbolAddress(&p, g_isrc);    int* isrc  = (int*)p;
    cudaGetSymbolAddress(&p, g_prow);    int* prow  = (int*)p;
    cudaGetSymbolAddress(&p, g_irow);    int* irow  = (int*)p;
    cudaGetSymbolAddress(&p, g_pcnt);    int* pcnt  = (int*)p;
    cudaGetSymbolAddress(&p, g_icnt);    int* icnt  = (int*)p;
    cudaGetSymbolAddress(&p, g_pbsum);   int* pbsum = (int*)p;
    cudaGetSymbolAddress(&p, g_ibsum);   int* ibsum = (int*)p;
    cudaGetSymbolAddress(&p, g_pcur);    int* pcur  = (int*)p;
    cudaGetSymbolAddress(&p, g_icur);    int* icur  = (int*)p;

    float* wi_hi  = whi;                float* wi_lo  = wlo;
    float* wp_hi  = whi + 1 * H * H;    float* wp_lo  = wlo + 1 * H * H;
    float* w2p_hi = whi + 2 * H * H;    float* w2p_lo = wlo + 2 * H * H;
    float* w2i_hi = whi + 3 * H * H;    float* w2i_lo = wlo + 3 * H * H;

    const int pblocks = (M_ + SCAN_B - 1) / SCAN_B;
    const int iblocks = (N_ + SCAN_B - 1) / SCAN_B;

    // ---- CSR build ----
    int nsamp = E_ / 2 < 1024 ? E_ / 2 : 1024;
    detect_kernel<<<1, 256>>>((const unsigned long long*)iidx_raw, nsamp);
    zero2_kernel<<<(N_ + 255) / 256, 256>>>(icnt, N_, pcnt, M_);
    count_kernel<<<(E_ + 255) / 256, 256>>>(iidx_raw, pidx_raw, E_);
    reduce_counts_kernel<<<pblocks, SCAN_B>>>(pcnt, M_, pbsum);
    scan_bsums_kernel<<<1, 1024>>>(pbsum, pblocks);
    scan_counts_kernel<<<pblocks, SCAN_B>>>(pcnt, M_, pbsum, prow, pcur, E_);
    reduce_counts_kernel<<<iblocks, SCAN_B>>>(icnt, N_, ibsum);
    scan_bsums_kernel<<<1, 1024>>>(ibsum, iblocks);
    scan_counts_kernel<<<iblocks, SCAN_B>>>(icnt, N_, ibsum, irow, icur, E_);
    place_kernel<<<(E_ + 255) / 256, 256>>>(E_);

    // ---- weight splits ----
    wsplit_kernel<<<(DI * H + 255) / 256, 256>>>(W_item, wi_hi,  wi_lo,  DI * H);
    wsplit_kernel<<<(DI * H + 255) / 256, 256>>>(W_pat,  wp_hi,  wp_lo,  DI * H);
    wsplit_kernel<<<(H * H + 255) / 256, 256>>>(W_i2p,  w2p_hi, w2p_lo, H * H);
    wsplit_kernel<<<(H * H + 255) / 256, 256>>>(W_p2i,  w2i_hi, w2i_lo, H * H);

    // ---- encoders (write fp32 state + fp16 mirrors) ----
    tgemm_kernel<DI, false><<<(N_ + 127) / 128, 256>>>(item_feat, wi_hi, wi_lo, b_item, h_item, hitem16, N_);
    tgemm_kernel<DI, false><<<(M_ + 127) / 128, 256>>>(pat_feat,  wp_hi, wp_lo, b_pat,  h_pat,  hpat16,  M_);

    const int pagg_blocks = (M_ * 32 + 255) / 256;
    const int iagg_blocks = (N_ * 32 + 255) / 256;

    for (int r = 0; r < 2; r++) {
        // item -> pattern (gather fp16 mirror, fp32 accumulate)
        aggregate_kernel<<<pagg_blocks, 256>>>(hitem16, pmsg, prow, psrc, M_);
        tgemm_kernel<H, true><<<(M_ + 127) / 128, 256>>>(pmsg, w2p_hi, w2p_lo, b_i2p, h_pat, hpat16, M_);
        // pattern -> item
        aggregate_kernel<<<iagg_blocks, 256>>>(hpat16, imsg, irow, isrc, N_);
        tgemm_kernel<H, true><<<(N_ + 127) / 128, 256>>>(imsg, w2i_hi, w2i_lo, b_p2i, h_item, hitem16, N_);
    }
}